// round 4
// baseline (speedup 1.0000x reference)
#include <cuda_runtime.h>
#include <math.h>

// ---------------- scratch (device globals: no allocation allowed) ----------------
__device__ float g_h1 [16u*256*1024];        // conv1 out, [b][p][hw]
__device__ float g_h1t[16u*1024*256];        // conv1 out, [b][hw][p] (channel-last for gather)
__device__ float g_off[16u*18*1024];         // offsets    [b][ch][hw]
__device__ float g_h2 [16u*256*1024];        // deform out [b][p][hw]
__device__ float g_w2t[256u*2304];           // w2 transposed to [o][k*256+c]
__device__ float g_acc[(size_t)16*1024*2304];// deform im2col [b][hw][k*256+c] (151MB)

#define BM 128
#define BN 128
#define BK 16

// ---------------- fused GEMM: C[b] = A(MxK) * B[b](KxN=1024), epi = BN(+shortcut)+ReLU ----
// BMODE 0: B stored row-major [K][1024]. BMODE 1: B stored [N][K] (transpose on load).
// EMODE 1: conv1 (writes C and channel-last copy C2). EMODE 2: deform. EMODE 3: conv3 (+shortcut).
template<int KT, int BMODE, int EMODE>
__global__ __launch_bounds__(256, 2)
void gemm_k(const float* __restrict__ A,
            const float* __restrict__ B, long strB,
            float* __restrict__ C, long strC,
            const float* __restrict__ eg, const float* __restrict__ eb,
            const float* __restrict__ em, const float* __restrict__ ev,
            const float* __restrict__ sc, long strS,
            float* __restrict__ C2)
{
    const int bz = blockIdx.z;
    const float* Bb = B + (long)bz * strB;
    float* Cb = C + (long)bz * strC;
    const int n0 = blockIdx.x * BN;
    const int m0 = blockIdx.y * BM;

    __shared__ float As[BK][BM];
    __shared__ float Bs[BK][BN];

    const int tid = threadIdx.x;
    const int tn = (tid & 15) * 8;
    const int tm = (tid >> 4) * 8;

    float acc[8][8];
#pragma unroll
    for (int i = 0; i < 8; i++)
#pragma unroll
        for (int j = 0; j < 8; j++) acc[i][j] = 0.f;

    float4 asg[2], bsg[2];

    auto ldA = [&](int kt){
#pragma unroll
        for (int q = 0; q < 2; q++){
            int s = tid*2 + q; int m = s >> 2; int kq = (s & 3) * 4;
            asg[q] = *reinterpret_cast<const float4*>(A + (long)(m0+m)*KT + kt + kq);
        }
    };
    auto ldB = [&](int kt){
#pragma unroll
        for (int q = 0; q < 2; q++){
            int s = tid*2 + q;
            if (BMODE == 0){ int k = s >> 5; int nq = (s & 31) * 4;
                bsg[q] = *reinterpret_cast<const float4*>(Bb + (long)(kt+k)*1024 + n0 + nq);
            } else { int n = s >> 2; int kq = (s & 3) * 4;
                bsg[q] = *reinterpret_cast<const float4*>(Bb + (long)(n0+n)*KT + kt + kq);
            }
        }
    };
    auto stA = [&](){
#pragma unroll
        for (int q = 0; q < 2; q++){
            int s = tid*2 + q; int m = s >> 2; int kq = (s & 3) * 4;
            As[kq+0][m] = asg[q].x; As[kq+1][m] = asg[q].y;
            As[kq+2][m] = asg[q].z; As[kq+3][m] = asg[q].w;
        }
    };
    auto stB = [&](){
#pragma unroll
        for (int q = 0; q < 2; q++){
            int s = tid*2 + q;
            if (BMODE == 0){ int k = s >> 5; int nq = (s & 31) * 4;
                *reinterpret_cast<float4*>(&Bs[k][nq]) = bsg[q];
            } else { int n = s >> 2; int kq = (s & 3) * 4;
                Bs[kq+0][n] = bsg[q].x; Bs[kq+1][n] = bsg[q].y;
                Bs[kq+2][n] = bsg[q].z; Bs[kq+3][n] = bsg[q].w;
            }
        }
    };

    ldA(0); ldB(0);
    stA(); stB();
    __syncthreads();

    for (int kt = BK; kt <= KT; kt += BK){
        bool more = kt < KT;
        if (more){ ldA(kt); ldB(kt); }
#pragma unroll
        for (int kk = 0; kk < BK; kk++){
            float ar[8], br[8];
            *reinterpret_cast<float4*>(ar)   = *reinterpret_cast<const float4*>(&As[kk][tm]);
            *reinterpret_cast<float4*>(ar+4) = *reinterpret_cast<const float4*>(&As[kk][tm+4]);
            *reinterpret_cast<float4*>(br)   = *reinterpret_cast<const float4*>(&Bs[kk][tn]);
            *reinterpret_cast<float4*>(br+4) = *reinterpret_cast<const float4*>(&Bs[kk][tn+4]);
#pragma unroll
            for (int i = 0; i < 8; i++)
#pragma unroll
                for (int j = 0; j < 8; j++)
                    acc[i][j] = fmaf(ar[i], br[j], acc[i][j]);
        }
        if (more){
            __syncthreads();
            stA(); stB();
            __syncthreads();
        }
    }

    // epilogue: BN (+shortcut for EMODE3), ReLU (all modes end in ReLU)
#pragma unroll
    for (int i = 0; i < 8; i++){
        int p = m0 + tm + i;
        float g = eg[p], be = eb[p], mm = em[p], vv = ev[p];
        float s = g / sqrtf(vv + 1e-5f);
        float t = be - mm * s;
#pragma unroll
        for (int j = 0; j < 8; j++){
            float c = acc[i][j] * s + t;
            if (EMODE == 3) c += sc[(long)bz*strS + (long)p*1024 + n0 + tn + j];
            acc[i][j] = fmaxf(c, 0.f);
        }
    }
#pragma unroll
    for (int i = 0; i < 8; i++){
        int p = m0 + tm + i;
        float4 v0 = make_float4(acc[i][0], acc[i][1], acc[i][2], acc[i][3]);
        float4 v1 = make_float4(acc[i][4], acc[i][5], acc[i][6], acc[i][7]);
        *reinterpret_cast<float4*>(Cb + (long)p*1024 + n0 + tn)     = v0;
        *reinterpret_cast<float4*>(Cb + (long)p*1024 + n0 + tn + 4) = v1;
    }
    if (EMODE == 1){
        float* C2b = C2 + (long)bz * (1024*256);
#pragma unroll
        for (int j = 0; j < 8; j++){
            int hw = n0 + tn + j;
            float4 v0 = make_float4(acc[0][j], acc[1][j], acc[2][j], acc[3][j]);
            float4 v1 = make_float4(acc[4][j], acc[5][j], acc[6][j], acc[7][j]);
            *reinterpret_cast<float4*>(C2b + (long)hw*256 + m0 + tm)     = v0;
            *reinterpret_cast<float4*>(C2b + (long)hw*256 + m0 + tm + 4) = v1;
        }
    }
}

// ---------------- w2 [O][C][3][3] -> w2t [O][k*256+c] ----------------
__global__ void w2t_k(const float* __restrict__ w2, float* __restrict__ w2t)
{
    long i = (long)blockIdx.x * 256 + threadIdx.x;
    if (i >= 256L*2304) return;
    int o = (int)(i / 2304); int r = (int)(i % 2304);
    int k = r / 256; int c = r % 256;
    w2t[i] = w2[(long)o*2304 + c*9 + k];
}

// ---------------- offset conv: 3x3, 256->18, pad 1, +bias ----------------
// grid = 16 b * 16 row-pairs; 288 threads = 2 rows * 18 oc * 8 xgroups(4x each)
// smem (dynamic 78336B): weights chunk [64c][18][9] + input slab [64c][4rows][36]
__global__ void offconv_k(const float* __restrict__ h1, const float* __restrict__ ow,
                          const float* __restrict__ ob, float* __restrict__ off)
{
    extern __shared__ float sm[];
    float* wsm  = sm;           // 10368 floats
    float* slab = sm + 10368;   // 9216 floats

    int b  = blockIdx.x >> 4;
    int yp = blockIdx.x & 15;
    int tid = threadIdx.x;
    int r   = tid / 144;        // 0..1 (output row within pair)
    int rem = tid % 144;
    int oc  = rem / 8;          // 0..17
    int xg  = rem % 8;          // 0..7 -> x = 4*xg..4*xg+3

    float a0 = 0.f, a1 = 0.f, a2 = 0.f, a3 = 0.f;
    const float* h1b = h1 + (long)b * (256*1024);

    for (int cc = 0; cc < 256; cc += 64){
        __syncthreads();
        for (int f = tid; f < 10368; f += 288){
            int c = f / 162; int r1 = f % 162; int o2 = r1 / 9; int kk = r1 % 9;
            wsm[f] = ow[((long)o2*256 + cc + c)*9 + kk];
        }
        for (int f = tid; f < 9216; f += 288){
            int c = f / 144; int rr = (f % 144) / 36; int xx = f % 36;
            int gy = yp*2 - 1 + rr;
            int gx = xx - 1;
            float v = 0.f;
            if (gy >= 0 && gy < 32 && gx >= 0 && gx < 32)
                v = h1b[(long)(cc + c)*1024 + gy*32 + gx];
            slab[f] = v;
        }
        __syncthreads();
#pragma unroll 4
        for (int c = 0; c < 64; c++){
            const float* wp = &wsm[c*162 + oc*9];
            const float* sp = &slab[c*144 + r*36 + xg*4];
#pragma unroll
            for (int ky = 0; ky < 3; ky++){
                float s0 = sp[ky*36+36*0+0]; // rows r..r+2 -> offset ky*36
                float s1, s2, s3, s4, s5;
                const float* q = sp + (ky+0)*36;
                s0 = q[0]; s1 = q[1]; s2 = q[2]; s3 = q[3]; s4 = q[4]; s5 = q[5];
                float w0 = wp[ky*3+0], w1 = wp[ky*3+1], w2v = wp[ky*3+2];
                a0 += s0*w0 + s1*w1 + s2*w2v;
                a1 += s1*w0 + s2*w1 + s3*w2v;
                a2 += s2*w0 + s3*w1 + s4*w2v;
                a3 += s3*w0 + s4*w1 + s5*w2v;
            }
        }
    }
    int yq = yp*2 + r;
    float bias = ob[oc];
    float* op = off + (long)b*(18*1024) + (long)oc*1024 + yq*32 + xg*4;
    op[0] = a0 + bias; op[1] = a1 + bias; op[2] = a2 + bias; op[3] = a3 + bias;
}

// ---------------- bilinear gather -> im2col acc[b][hw][k*256+c] ----------------
// grid = 16 b * 32 y; 256 threads = 4 parallel (k,x)-jobs * 64 c-float4 lanes
__global__ void gather_k(const float* __restrict__ h1t, const float* __restrict__ off,
                         float* __restrict__ acc)
{
    int b = blockIdx.x >> 5;
    int y = blockIdx.x & 31;
    int lane = threadIdx.x & 63;
    int jg   = threadIdx.x >> 6;
    const float* h1b  = h1t + (long)b * (1024*256);
    const float* offb = off + (long)b * (18*1024);
    float* accb = acc + (long)b * (1024L*2304);

    for (int j = jg; j < 288; j += 4){
        int k = j >> 5;
        int x = j & 31;
        int pix = y*32 + x;
        float oy = offb[(2*k  )*1024 + pix];
        float ox = offb[(2*k+1)*1024 + pix];
        float py = (float)y + (float)(k/3 - 1) + oy;
        float px = (float)x + (float)(k%3 - 1) + ox;
        float y0f = floorf(py), x0f = floorf(px);
        float wy = py - y0f, wx = px - x0f;

        float rx = 0.f, ry = 0.f, rz = 0.f, rw = 0.f;
#pragma unroll
        for (int dy = 0; dy < 2; dy++)
#pragma unroll
        for (int dx = 0; dx < 2; dx++){
            float yi = y0f + (float)dy, xi = x0f + (float)dx;
            float w = (dy ? wy : 1.f - wy) * (dx ? wx : 1.f - wx);
            bool valid = (yi >= 0.f) && (yi <= 31.f) && (xi >= 0.f) && (xi <= 31.f);
            w = valid ? w : 0.f;
            int yic = (int)fminf(fmaxf(yi, 0.f), 31.f);
            int xic = (int)fminf(fmaxf(xi, 0.f), 31.f);
            float4 g = *reinterpret_cast<const float4*>(h1b + (long)(yic*32 + xic)*256 + lane*4);
            rx = fmaf(w, g.x, rx); ry = fmaf(w, g.y, ry);
            rz = fmaf(w, g.z, rz); rw = fmaf(w, g.w, rw);
        }
        *reinterpret_cast<float4*>(accb + (long)pix*2304 + k*256 + lane*4)
            = make_float4(rx, ry, rz, rw);
    }
}

// ---------------- launch ----------------
extern "C" void kernel_launch(void* const* d_in, const int* in_sizes, int n_in,
                              void* d_out, int out_size)
{
    const float* x    = (const float*)d_in[0];
    const float* w1   = (const float*)d_in[1];
    const float* bn1g = (const float*)d_in[2];
    const float* bn1b = (const float*)d_in[3];
    const float* bn1m = (const float*)d_in[4];
    const float* bn1v = (const float*)d_in[5];
    const float* offw = (const float*)d_in[6];
    const float* offb = (const float*)d_in[7];
    const float* w2   = (const float*)d_in[8];
    const float* bn2g = (const float*)d_in[9];
    const float* bn2b = (const float*)d_in[10];
    const float* bn2m = (const float*)d_in[11];
    const float* bn2v = (const float*)d_in[12];
    const float* w3   = (const float*)d_in[13];
    const float* bn3g = (const float*)d_in[14];
    const float* bn3b = (const float*)d_in[15];
    const float* bn3m = (const float*)d_in[16];
    const float* bn3v = (const float*)d_in[17];
    float* out = (float*)d_out;

    float *p_h1, *p_h1t, *p_off, *p_h2, *p_w2t, *p_acc;
    cudaGetSymbolAddress((void**)&p_h1,  g_h1);
    cudaGetSymbolAddress((void**)&p_h1t, g_h1t);
    cudaGetSymbolAddress((void**)&p_off, g_off);
    cudaGetSymbolAddress((void**)&p_h2,  g_h2);
    cudaGetSymbolAddress((void**)&p_w2t, g_w2t);
    cudaGetSymbolAddress((void**)&p_acc, g_acc);

    cudaFuncSetAttribute(offconv_k, cudaFuncAttributeMaxDynamicSharedMemorySize, 78336);

    // w2 transpose (tiny)
    w2t_k<<<2304, 256>>>(w2, p_w2t);

    // conv1x1 (1024->256) + BN1 + ReLU, write [p][hw] and [hw][p]
    gemm_k<1024, 0, 1><<<dim3(8, 2, 16), 256>>>(
        w1, x, 1024L*1024, p_h1, 256L*1024,
        bn1g, bn1b, bn1m, bn1v, nullptr, 0, p_h1t);

    // offset conv 3x3 (256->18) + bias
    offconv_k<<<256, 288, 78336>>>(p_h1, offw, offb, p_off);

    // deformable bilinear gather -> im2col
    gather_k<<<512, 256>>>(p_h1t, p_off, p_acc);

    // deform conv as GEMM over K=2304 + BN2 + ReLU
    gemm_k<2304, 1, 2><<<dim3(8, 2, 16), 256>>>(
        p_w2t, p_acc, 1024L*2304, p_h2, 256L*1024,
        bn2g, bn2b, bn2m, bn2v, nullptr, 0, nullptr);

    // conv1x1 (256->1024) + BN3 + shortcut + ReLU -> d_out
    gemm_k<256, 0, 3><<<dim3(8, 8, 16), 256>>>(
        w3, p_h2, 256L*1024, out, 1024L*1024,
        bn3g, bn3b, bn3m, bn3v, x, 1024L*1024, nullptr);

    (void)in_sizes; (void)n_in; (void)out_size;
}

// round 6
// speedup vs baseline: 2.5544x; 2.5544x over previous
#include <cuda_runtime.h>
#include <math.h>
#include <stdint.h>

// ---------------- scratch (device globals: no allocation allowed) ----------------
__device__ float g_h1 [16u*256*1024];        // conv1 out, [b][p][hw]  (fp32, for offconv)
__device__ float g_h1t[16u*1024*256];        // conv1 out, [b][hw][p]  (fp32, for gather)
__device__ float g_off[16u*18*1024];         // offsets    [b][ch][hw]
__device__ float g_h2t[16u*1024*256];        // deform out [b][hw][p]  (tf32-rounded, B of conv3)
__device__ float g_w2t[256u*2304];           // w2 -> [o][k*256+c]     (tf32-rounded)
__device__ float g_w1r[256u*1024];           // w1 tf32-rounded
__device__ float g_w3r[1024u*256];           // w3 tf32-rounded
__device__ float g_xt [(size_t)16*1024*1024];// x transposed [b][hw][c] tf32-rounded (B of conv1)
__device__ float g_acc[(size_t)16*1024*2304];// deform im2col [b][hw][k*256+c] (tf32-rounded)

// ============================ helpers ============================
__device__ __forceinline__ uint32_t smem_u32(const void* p){
    uint32_t a;
    asm("{ .reg .u64 t; cvta.to.shared.u64 t, %1; cvt.u32.u64 %0, t; }" : "=r"(a) : "l"(p));
    return a;
}
__device__ __forceinline__ float rtf32(float x){
    uint32_t r; asm("cvt.rna.tf32.f32 %0, %1;" : "=r"(r) : "f"(x));
    return __uint_as_float(r);
}
__device__ __forceinline__ void cp16(uint32_t dst, const float* src){
    asm volatile("cp.async.ca.shared.global [%0], [%1], 16;" :: "r"(dst), "l"(src) : "memory");
}
__device__ __forceinline__ void cp_commit(){
    asm volatile("cp.async.commit_group;" ::: "memory");
}
template<int N>
__device__ __forceinline__ void cp_wait(){
    asm volatile("cp.async.wait_group %0;" :: "n"(N) : "memory");
}
// tf32 tensor-core mma: D(16x8) += A(16x8) * B(8x8)
__device__ __forceinline__ void mma8(float* c, const uint32_t* a, const uint32_t* b){
    asm volatile(
        "mma.sync.aligned.m16n8k8.row.col.f32.tf32.tf32.f32 "
        "{%0,%1,%2,%3}, {%4,%5,%6,%7}, {%8,%9}, {%0,%1,%2,%3};"
        : "+f"(c[0]), "+f"(c[1]), "+f"(c[2]), "+f"(c[3])
        : "r"(a[0]), "r"(a[1]), "r"(a[2]), "r"(a[3]), "r"(b[0]), "r"(b[1]));
}

// ============== TF32 mma.sync GEMM: C[b](128x128 tile) = A(MxK) * B[b](N rows, K-major) =====
// A: [M][K] row-major weights (no batch stride). B: [N][K] rows per batch.
// EMODE 1: conv1  -> BN+ReLU; write C=[p][hw] direct AND C2=[hw][p] (smem transpose).
// EMODE 2: deform -> BN+ReLU+tf32-round; write ONLY C2=[hw][p].
// EMODE 3: conv3  -> BN + shortcut + ReLU; write C direct.
#define TG_SMEM 73728
template<int KT, int EMODE>
__global__ __launch_bounds__(256, 2)
void tgemm_k(const float* __restrict__ A,
             const float* __restrict__ B, long strB,
             float* __restrict__ C, long strC,
             const float* __restrict__ eg, const float* __restrict__ eb,
             const float* __restrict__ em, const float* __restrict__ ev,
             const float* __restrict__ sc, long strS,
             float* __restrict__ C2, long strC2)
{
    extern __shared__ char smem_raw[];
    float* sf = (float*)smem_raw;
    const uint32_t sbase = smem_u32(smem_raw);

    const int tid  = threadIdx.x;
    const int lane = tid & 31, wid = tid >> 5;
    const int bz = blockIdx.z;
    const int n0 = blockIdx.x * 128, m0 = blockIdx.y * 128;
    const float* Bb = B + (size_t)bz * strB;
    const int wm = wid & 1;       // 2 strips of 64 rows
    const int wn = wid >> 1;      // 4 strips of 32 cols

    float acc[4][4][4];
#pragma unroll
    for (int mt = 0; mt < 4; mt++)
#pragma unroll
        for (int nt = 0; nt < 4; nt++)
#pragma unroll
            for (int c = 0; c < 4; c++) acc[mt][nt][c] = 0.f;

    // smem: buf0 A@0 B@18432, buf1 A@36864 B@55296 (row stride 36 floats = 144B)
    auto issue = [&](int kt, int buf){
        uint32_t dA = sbase + (uint32_t)buf * 36864u;
        uint32_t dB = dA + 18432u;
#pragma unroll
        for (int q = 0; q < 4; q++){
            int f = q * 256 + tid; int m = f >> 3, k4 = f & 7;
            cp16(dA + (uint32_t)(m * 144 + k4 * 16), A + (size_t)(m0 + m) * KT + kt * 32 + k4 * 4);
        }
#pragma unroll
        for (int q = 0; q < 4; q++){
            int f = q * 256 + tid; int n = f >> 3, k4 = f & 7;
            cp16(dB + (uint32_t)(n * 144 + k4 * 16), Bb + (size_t)(n0 + n) * KT + kt * 32 + k4 * 4);
        }
    };

    constexpr int T = KT / 32;
    issue(0, 0); cp_commit();

    const int kbase = lane & 3;
    const int r0 = wm * 64 + (lane >> 2);
    const int c0 = wn * 32 + (lane >> 2);

    for (int kt = 0; kt < T; kt++){
        const int cur = kt & 1;
        if (kt + 1 < T) issue(kt + 1, 1 - cur);
        cp_commit();
        cp_wait<1>();
        __syncthreads();

        const float* As = sf + cur * 9216;
        const float* Bs = As + 4608;
#pragma unroll
        for (int ks = 0; ks < 4; ks++){
            const int kk = ks * 8 + kbase;
            uint32_t af[4][4], bf[4][2];
#pragma unroll
            for (int mt = 0; mt < 4; mt++){
                const float* ap = As + (r0 + mt * 16) * 36 + kk;
                af[mt][0] = __float_as_uint(ap[0]);
                af[mt][1] = __float_as_uint(ap[288]);   // +8 rows
                af[mt][2] = __float_as_uint(ap[4]);     // +4 k
                af[mt][3] = __float_as_uint(ap[292]);
            }
#pragma unroll
            for (int nt = 0; nt < 4; nt++){
                const float* bp = Bs + (c0 + nt * 8) * 36 + kk;
                bf[nt][0] = __float_as_uint(bp[0]);
                bf[nt][1] = __float_as_uint(bp[4]);
            }
#pragma unroll
            for (int mt = 0; mt < 4; mt++)
#pragma unroll
                for (int nt = 0; nt < 4; nt++)
                    mma8(acc[mt][nt], af[mt], bf[nt]);
        }
        __syncthreads();
    }

    // ---------------- epilogue ----------------
    float bs[4][2], bt[4][2];
#pragma unroll
    for (int mt = 0; mt < 4; mt++)
#pragma unroll
        for (int d = 0; d < 2; d++){
            int p = m0 + wm * 64 + mt * 16 + (lane >> 2) + 8 * d;
            float s = eg[p] * rsqrtf(ev[p] + 1e-5f);
            bs[mt][d] = s; bt[mt][d] = eb[p] - em[p] * s;
        }

#pragma unroll
    for (int mt = 0; mt < 4; mt++)
#pragma unroll
        for (int nt = 0; nt < 4; nt++)
#pragma unroll
            for (int c = 0; c < 4; c++)
                acc[mt][nt][c] = acc[mt][nt][c] * bs[mt][c >> 1] + bt[mt][c >> 1];

    if (EMODE == 3){
#pragma unroll
        for (int mt = 0; mt < 4; mt++)
#pragma unroll
            for (int nt = 0; nt < 4; nt++)
#pragma unroll
                for (int d = 0; d < 2; d++){
                    int p   = m0 + wm * 64 + mt * 16 + (lane >> 2) + 8 * d;
                    int col = n0 + wn * 32 + nt * 8 + 2 * (lane & 3);
                    float2 u = *reinterpret_cast<const float2*>(sc + (size_t)bz * strS + (size_t)p * 1024 + col);
                    acc[mt][nt][2 * d]     += u.x;
                    acc[mt][nt][2 * d + 1] += u.y;
                }
    }
#pragma unroll
    for (int mt = 0; mt < 4; mt++)
#pragma unroll
        for (int nt = 0; nt < 4; nt++)
#pragma unroll
            for (int c = 0; c < 4; c++){
                float v = fmaxf(acc[mt][nt][c], 0.f);
                if (EMODE == 2) v = rtf32(v);
                acc[mt][nt][c] = v;
            }

    if (EMODE == 1 || EMODE == 3){
        float* Cb = C + (size_t)bz * strC;
#pragma unroll
        for (int mt = 0; mt < 4; mt++)
#pragma unroll
            for (int nt = 0; nt < 4; nt++)
#pragma unroll
                for (int d = 0; d < 2; d++){
                    int p   = m0 + wm * 64 + mt * 16 + (lane >> 2) + 8 * d;
                    int col = n0 + wn * 32 + nt * 8 + 2 * (lane & 3);
                    *reinterpret_cast<float2*>(Cb + (size_t)p * 1024 + col) =
                        make_float2(acc[mt][nt][2 * d], acc[mt][nt][2 * d + 1]);
                }
    }

    if (EMODE == 1 || EMODE == 2){
        // smem transpose: tile [p][hw] -> [hw][p], row stride 132 (conflict-free)
        __syncthreads();
#pragma unroll
        for (int mt = 0; mt < 4; mt++)
#pragma unroll
            for (int nt = 0; nt < 4; nt++)
#pragma unroll
                for (int c = 0; c < 4; c++){
                    int rl = wm * 64 + mt * 16 + (lane >> 2) + 8 * (c >> 1);
                    int cl = wn * 32 + nt * 8 + 2 * (lane & 3) + (c & 1);
                    sf[cl * 132 + rl] = acc[mt][nt][c];
                }
        __syncthreads();
        float* C2b = C2 + (size_t)bz * strC2;
#pragma unroll
        for (int q = 0; q < 16; q++){
            int i = q * 256 + tid;
            int hw = i >> 5, p4 = (i & 31) * 4;
            float4 vv = *reinterpret_cast<const float4*>(sf + hw * 132 + p4);
            *reinterpret_cast<float4*>(C2b + (size_t)(n0 + hw) * 256 + m0 + p4) = vv;
        }
    }
}

// ---------------- x [b][c][hw] -> xt [b][hw][c], tf32-rounded ----------------
__global__ void xt_k(const float* __restrict__ x, float* __restrict__ xt)
{
    __shared__ float t[32][33];
    int b = blockIdx.z;
    int c0 = blockIdx.x * 32, h0 = blockIdx.y * 32;
    const float* xb = x + (size_t)b * 1048576;
    float* xtb = xt + (size_t)b * 1048576;
#pragma unroll
    for (int i = 0; i < 32; i += 8)
        t[threadIdx.y + i][threadIdx.x] = xb[(size_t)(c0 + threadIdx.y + i) * 1024 + h0 + threadIdx.x];
    __syncthreads();
#pragma unroll
    for (int i = 0; i < 32; i += 8)
        xtb[(size_t)(h0 + threadIdx.y + i) * 1024 + c0 + threadIdx.x] = rtf32(t[threadIdx.x][threadIdx.y + i]);
}

// ---------------- tf32 rounding (vectorized) ----------------
__global__ void round4_k(const float4* __restrict__ s, float4* __restrict__ d, int n4)
{
    int i = blockIdx.x * blockDim.x + threadIdx.x;
    if (i < n4){
        float4 v = s[i];
        d[i] = make_float4(rtf32(v.x), rtf32(v.y), rtf32(v.z), rtf32(v.w));
    }
}

// ---------------- w2 [O][C][3][3] -> w2t [O][k*256+c] (tf32-rounded) ----------------
__global__ void w2t_k(const float* __restrict__ w2, float* __restrict__ w2t)
{
    long i = (long)blockIdx.x * 256 + threadIdx.x;
    if (i >= 256L * 2304) return;
    int o = (int)(i / 2304); int r = (int)(i % 2304);
    int k = r / 256; int c = r % 256;
    w2t[i] = rtf32(w2[(long)o * 2304 + c * 9 + k]);
}

// ---------------- offset conv: 3x3, 256->18, pad 1, +bias ----------------
__global__ void offconv_k(const float* __restrict__ h1, const float* __restrict__ ow,
                          const float* __restrict__ ob, float* __restrict__ off)
{
    extern __shared__ float sm[];
    float* wsm  = sm;           // 10368 floats
    float* slab = sm + 10368;   // 9216 floats

    int b  = blockIdx.x >> 4;
    int yp = blockIdx.x & 15;
    int tid = threadIdx.x;
    int r   = tid / 144;
    int rem = tid % 144;
    int oc  = rem / 8;
    int xg  = rem % 8;

    float a0 = 0.f, a1 = 0.f, a2 = 0.f, a3 = 0.f;
    const float* h1b = h1 + (long)b * (256 * 1024);

    for (int cc = 0; cc < 256; cc += 64){
        __syncthreads();
        for (int f = tid; f < 10368; f += 288){
            int c = f / 162; int r1 = f % 162; int o2 = r1 / 9; int kk = r1 % 9;
            wsm[f] = ow[((long)o2 * 256 + cc + c) * 9 + kk];
        }
        for (int f = tid; f < 9216; f += 288){
            int c = f / 144; int rr2 = (f % 144) / 36; int xx = f % 36;
            int gy = yp * 2 - 1 + rr2;
            int gx = xx - 1;
            float vv = 0.f;
            if (gy >= 0 && gy < 32 && gx >= 0 && gx < 32)
                vv = h1b[(long)(cc + c) * 1024 + gy * 32 + gx];
            slab[f] = vv;
        }
        __syncthreads();
#pragma unroll 4
        for (int c = 0; c < 64; c++){
            const float* wp = &wsm[c * 162 + oc * 9];
            const float* sp = &slab[c * 144 + r * 36 + xg * 4];
#pragma unroll
            for (int ky = 0; ky < 3; ky++){
                const float* q = sp + ky * 36;
                float s_0 = q[0], s_1 = q[1], s_2 = q[2], s_3 = q[3], s_4 = q[4], s_5 = q[5];
                float w0 = wp[ky*3+0], w1 = wp[ky*3+1], w2v = wp[ky*3+2];
                a0 += s_0*w0 + s_1*w1 + s_2*w2v;
                a1 += s_1*w0 + s_2*w1 + s_3*w2v;
                a2 += s_2*w0 + s_3*w1 + s_4*w2v;
                a3 += s_3*w0 + s_4*w1 + s_5*w2v;
            }
        }
    }
    int yq = yp * 2 + r;
    float bias = ob[oc];
    float* op = off + (long)b * (18 * 1024) + (long)oc * 1024 + yq * 32 + xg * 4;
    op[0] = a0 + bias; op[1] = a1 + bias; op[2] = a2 + bias; op[3] = a3 + bias;
}

// ---------------- bilinear gather -> im2col acc[b][hw][k*256+c] (tf32-rounded) ---------
__global__ void gather_k(const float* __restrict__ h1t, const float* __restrict__ off,
                         float* __restrict__ acc)
{
    int b = blockIdx.x >> 5;
    int y = blockIdx.x & 31;
    int lane = threadIdx.x & 63;
    int jg   = threadIdx.x >> 6;
    const float* h1b  = h1t + (long)b * (1024 * 256);
    const float* offb = off + (long)b * (18 * 1024);
    float* accb = acc + (long)b * (1024L * 2304);

    for (int j = jg; j < 288; j += 4){
        int k = j >> 5;
        int x = j & 31;
        int pix = y * 32 + x;
        float oy = offb[(2*k  ) * 1024 + pix];
        float ox = offb[(2*k+1) * 1024 + pix];
        float py = (float)y + (float)(k / 3 - 1) + oy;
        float px = (float)x + (float)(k % 3 - 1) + ox;
        float y0f = floorf(py), x0f = floorf(px);
        float wy = py - y0f, wx = px - x0f;

        float rx = 0.f, ry = 0.f, rz = 0.f, rw = 0.f;
#pragma unroll
        for (int dy = 0; dy < 2; dy++)
#pragma unroll
        for (int dx = 0; dx < 2; dx++){
            float yi = y0f + (float)dy, xi = x0f + (float)dx;
            float w = (dy ? wy : 1.f - wy) * (dx ? wx : 1.f - wx);
            bool valid = (yi >= 0.f) && (yi <= 31.f) && (xi >= 0.f) && (xi <= 31.f);
            w = valid ? w : 0.f;
            int yic = (int)fminf(fmaxf(yi, 0.f), 31.f);
            int xic = (int)fminf(fmaxf(xi, 0.f), 31.f);
            float4 g = *reinterpret_cast<const float4*>(h1b + (long)(yic * 32 + xic) * 256 + lane * 4);
            rx = fmaf(w, g.x, rx); ry = fmaf(w, g.y, ry);
            rz = fmaf(w, g.z, rz); rw = fmaf(w, g.w, rw);
        }
        *reinterpret_cast<float4*>(accb + (long)pix * 2304 + k * 256 + lane * 4)
            = make_float4(rtf32(rx), rtf32(ry), rtf32(rz), rtf32(rw));
    }
}

// ---------------- launch ----------------
extern "C" void kernel_launch(void* const* d_in, const int* in_sizes, int n_in,
                              void* d_out, int out_size)
{
    const float* x    = (const float*)d_in[0];
    const float* w1   = (const float*)d_in[1];
    const float* bn1g = (const float*)d_in[2];
    const float* bn1b = (const float*)d_in[3];
    const float* bn1m = (const float*)d_in[4];
    const float* bn1v = (const float*)d_in[5];
    const float* offw = (const float*)d_in[6];
    const float* offb = (const float*)d_in[7];
    const float* w2   = (const float*)d_in[8];
    const float* bn2g = (const float*)d_in[9];
    const float* bn2b = (const float*)d_in[10];
    const float* bn2m = (const float*)d_in[11];
    const float* bn2v = (const float*)d_in[12];
    const float* w3   = (const float*)d_in[13];
    const float* bn3g = (const float*)d_in[14];
    const float* bn3b = (const float*)d_in[15];
    const float* bn3m = (const float*)d_in[16];
    const float* bn3v = (const float*)d_in[17];
    float* out = (float*)d_out;

    float *p_h1, *p_h1t, *p_off, *p_h2t, *p_w2t, *p_acc, *p_w1r, *p_w3r, *p_xt;
    cudaGetSymbolAddress((void**)&p_h1,  g_h1);
    cudaGetSymbolAddress((void**)&p_h1t, g_h1t);
    cudaGetSymbolAddress((void**)&p_off, g_off);
    cudaGetSymbolAddress((void**)&p_h2t, g_h2t);
    cudaGetSymbolAddress((void**)&p_w2t, g_w2t);
    cudaGetSymbolAddress((void**)&p_acc, g_acc);
    cudaGetSymbolAddress((void**)&p_w1r, g_w1r);
    cudaGetSymbolAddress((void**)&p_w3r, g_w3r);
    cudaGetSymbolAddress((void**)&p_xt,  g_xt);

    cudaFuncSetAttribute(offconv_k, cudaFuncAttributeMaxDynamicSharedMemorySize, 78336);
    cudaFuncSetAttribute(tgemm_k<1024,1>, cudaFuncAttributeMaxDynamicSharedMemorySize, TG_SMEM);
    cudaFuncSetAttribute(tgemm_k<2304,2>, cudaFuncAttributeMaxDynamicSharedMemorySize, TG_SMEM);
    cudaFuncSetAttribute(tgemm_k<256,3>,  cudaFuncAttributeMaxDynamicSharedMemorySize, TG_SMEM);

    // operand prep (tf32 rounding; x also transposed to [hw][c])
    xt_k<<<dim3(32, 32, 16), dim3(32, 8)>>>(x, p_xt);
    round4_k<<<256, 256>>>((const float4*)w1, (float4*)p_w1r, 256 * 1024 / 4);
    round4_k<<<256, 256>>>((const float4*)w3, (float4*)p_w3r, 1024 * 256 / 4);
    w2t_k<<<2304, 256>>>(w2, p_w2t);

    // conv1x1 (1024->256) + BN1 + ReLU -> h1 [p][hw] + h1t [hw][p]   [tensor core tf32]
    tgemm_k<1024,1><<<dim3(8, 2, 16), 256, TG_SMEM>>>(
        p_w1r, p_xt, 1048576L, p_h1, 262144L,
        bn1g, bn1b, bn1m, bn1v, nullptr, 0, p_h1t, 262144L);

    // offset conv 3x3 (256->18) + bias
    offconv_k<<<256, 288, 78336>>>(p_h1, offw, offb, p_off);

    // deformable bilinear gather -> im2col (tf32-rounded)
    gather_k<<<512, 256>>>(p_h1t, p_off, p_acc);

    // deform conv GEMM K=2304 + BN2 + ReLU -> h2t [hw][p] (rounded)  [tensor core tf32]
    tgemm_k<2304,2><<<dim3(8, 2, 16), 256, TG_SMEM>>>(
        p_w2t, p_acc, 2359296L, nullptr, 0,
        bn2g, bn2b, bn2m, bn2v, nullptr, 0, p_h2t, 262144L);

    // conv1x1 (256->1024) + BN3 + shortcut + ReLU -> d_out          [tensor core tf32]
    tgemm_k<256,3><<<dim3(8, 8, 16), 256, TG_SMEM>>>(
        p_w3r, p_h2t, 262144L, out, 1048576L,
        bn3g, bn3b, bn3m, bn3v, x, 1048576L, nullptr, 0);

    (void)in_sizes; (void)n_in; (void)out_size;
}

// round 8
// speedup vs baseline: 3.0649x; 1.1999x over previous
#include <cuda_runtime.h>
#include <cuda_fp16.h>
#include <math.h>
#include <stdint.h>

// ---------------- scratch (device globals: no allocation allowed) ----------------
__device__ float  g_h1 [16u*256*1024];         // conv1 out, [b][p][hw] fp32 (offconv input)
__device__ __half g_h1t[16u*1024*256];         // conv1 out, [b][hw][p] fp16 (gather input)
__device__ float  g_off[16u*18*1024];          // offsets    [b][ch][hw] fp32
__device__ __half g_h2h[16u*1024*256];         // deform out [b][hw][p] fp16 (conv3 B)
__device__ __half g_w1h[256u*1024];            // w1 fp16
__device__ __half g_w2h[256u*2304];            // w2 -> [o][tap*256+c] fp16
__device__ __half g_w3h[1024u*256];            // w3 fp16
__device__ __half g_xh [(size_t)16*1024*1024]; // x transposed [b][hw][c] fp16 (conv1 B)
__device__ __half g_acch[(size_t)16*1024*2304];// deform im2col [b][hw][tap*256+c] fp16 (75MB)

// ============================ helpers ============================
__device__ __forceinline__ uint32_t smem_u32(const void* p){
    uint32_t a;
    asm("{ .reg .u64 t; cvta.to.shared.u64 t, %1; cvt.u32.u64 %0, t; }" : "=r"(a) : "l"(p));
    return a;
}
__device__ __forceinline__ void cp16(uint32_t dst, const void* src){
    asm volatile("cp.async.ca.shared.global [%0], [%1], 16;" :: "r"(dst), "l"(src) : "memory");
}
__device__ __forceinline__ void cp_commit(){
    asm volatile("cp.async.commit_group;" ::: "memory");
}
template<int N>
__device__ __forceinline__ void cp_wait(){
    asm volatile("cp.async.wait_group %0;" :: "n"(N) : "memory");
}
// fp16 tensor-core mma: D(16x8,f32) += A(16x16,f16) * B(16x8,f16)
__device__ __forceinline__ void mma16(float* c, const uint32_t* a, const uint32_t* b){
    asm volatile(
        "mma.sync.aligned.m16n8k16.row.col.f32.f16.f16.f32 "
        "{%0,%1,%2,%3}, {%4,%5,%6,%7}, {%8,%9}, {%0,%1,%2,%3};"
        : "+f"(c[0]), "+f"(c[1]), "+f"(c[2]), "+f"(c[3])
        : "r"(a[0]), "r"(a[1]), "r"(a[2]), "r"(a[3]), "r"(b[0]), "r"(b[1]));
}

// ============== fp16 mma GEMM: C[b](128x128 tile) = A(MxK) * B[b](N rows, K-major) =====
// A: [M][K] fp16 weights (no batch stride). B: [N][K] fp16 rows per batch.
// Smem rows padded to 40 halfs (20 words): frag loads provably bank-conflict-free.
// EMODE 1: conv1  -> BN+ReLU; write C fp32 [p][hw] AND C2 fp16 [hw][p] (smem transpose).
// EMODE 2: deform -> BN+ReLU; write ONLY C2 fp16 [hw][p].
// EMODE 3: conv3  -> BN + shortcut + ReLU; write C fp32.
#define TGH_SMEM 61440    // 3 stages x (A 10240B + B 10240B); epilogue transpose reuses 34816B
template<int KT, int EMODE>
__global__ __launch_bounds__(256, 2)
void tgemm_h(const __half* __restrict__ A,
             const __half* __restrict__ B, long strB,
             float* __restrict__ C, long strC,
             const float* __restrict__ eg, const float* __restrict__ eb,
             const float* __restrict__ em, const float* __restrict__ ev,
             const float* __restrict__ sc, long strS,
             __half* __restrict__ C2, long strC2)
{
    extern __shared__ char smem_raw[];
    const uint32_t sbase = smem_u32(smem_raw);

    const int tid  = threadIdx.x;
    const int lane = tid & 31, wid = tid >> 5;
    const int bz = blockIdx.z;
    const int n0 = blockIdx.x * 128, m0 = blockIdx.y * 128;
    const __half* Bb = B + (size_t)bz * strB;
    const int wm = wid & 1;       // 2 strips of 64 rows
    const int wn = wid >> 1;      // 4 strips of 32 cols
    const int r0 = lane >> 2, kb0 = lane & 3;

    float acc[4][4][4];
#pragma unroll
    for (int mt = 0; mt < 4; mt++)
#pragma unroll
        for (int nt = 0; nt < 4; nt++)
#pragma unroll
            for (int c = 0; c < 4; c++) acc[mt][nt][c] = 0.f;

    // stage buf: A@buf*20480 (128 rows x 80B), B@+10240
    auto issue = [&](int kt, int buf){
        uint32_t dA = sbase + (uint32_t)buf * 20480u;
        uint32_t dB = dA + 10240u;
#pragma unroll
        for (int q = 0; q < 2; q++){
            int f = q * 256 + tid; int m = f >> 2, k8 = f & 3;
            cp16(dA + (uint32_t)(m * 80 + k8 * 16), A + (size_t)(m0 + m) * KT + kt * 32 + k8 * 8);
        }
#pragma unroll
        for (int q = 0; q < 2; q++){
            int f = q * 256 + tid; int n = f >> 2, k8 = f & 3;
            cp16(dB + (uint32_t)(n * 80 + k8 * 16), Bb + (size_t)(n0 + n) * KT + kt * 32 + k8 * 8);
        }
    };

    constexpr int T = KT / 32;
    issue(0, 0); cp_commit();
    issue(1, 1); cp_commit();

    int cur = 0;
    for (int kt = 0; kt < T; kt++){
        if (kt + 2 < T){
            int nb = cur + 2; if (nb >= 3) nb -= 3;
            issue(kt + 2, nb);
        }
        cp_commit();
        cp_wait<2>();
        __syncthreads();

        const uint32_t* Aw = (const uint32_t*)(smem_raw + cur * 20480);
        const uint32_t* Bw = Aw + 2560;
#pragma unroll
        for (int ks = 0; ks < 2; ks++){
            const int kb = ks * 8 + kb0;
            uint32_t af[4][4], bf[4][2];
#pragma unroll
            for (int mt = 0; mt < 4; mt++){
                const uint32_t* ap = Aw + (wm * 64 + mt * 16 + r0) * 20 + kb;
                af[mt][0] = ap[0];   af[mt][1] = ap[160];
                af[mt][2] = ap[4];   af[mt][3] = ap[164];
            }
#pragma unroll
            for (int nt = 0; nt < 4; nt++){
                const uint32_t* bp = Bw + (wn * 32 + nt * 8 + r0) * 20 + kb;
                bf[nt][0] = bp[0];   bf[nt][1] = bp[4];
            }
#pragma unroll
            for (int mt = 0; mt < 4; mt++)
#pragma unroll
                for (int nt = 0; nt < 4; nt++)
                    mma16(acc[mt][nt], af[mt], bf[nt]);
        }
        __syncthreads();
        if (++cur == 3) cur = 0;
    }

    // ---------------- epilogue ----------------
    float bs[4][2], bt[4][2];
#pragma unroll
    for (int mt = 0; mt < 4; mt++)
#pragma unroll
        for (int d = 0; d < 2; d++){
            int p = m0 + wm * 64 + mt * 16 + r0 + 8 * d;
            float s = eg[p] * rsqrtf(ev[p] + 1e-5f);
            bs[mt][d] = s; bt[mt][d] = eb[p] - em[p] * s;
        }

#pragma unroll
    for (int mt = 0; mt < 4; mt++)
#pragma unroll
        for (int nt = 0; nt < 4; nt++)
#pragma unroll
            for (int c = 0; c < 4; c++)
                acc[mt][nt][c] = acc[mt][nt][c] * bs[mt][c >> 1] + bt[mt][c >> 1];

    if (EMODE == 3){
#pragma unroll
        for (int mt = 0; mt < 4; mt++)
#pragma unroll
            for (int nt = 0; nt < 4; nt++)
#pragma unroll
                for (int d = 0; d < 2; d++){
                    int p   = m0 + wm * 64 + mt * 16 + r0 + 8 * d;
                    int col = n0 + wn * 32 + nt * 8 + 2 * (lane & 3);
                    float2 u = *reinterpret_cast<const float2*>(sc + (size_t)bz * strS + (size_t)p * 1024 + col);
                    acc[mt][nt][2 * d]     += u.x;
                    acc[mt][nt][2 * d + 1] += u.y;
                }
    }
#pragma unroll
    for (int mt = 0; mt < 4; mt++)
#pragma unroll
        for (int nt = 0; nt < 4; nt++)
#pragma unroll
            for (int c = 0; c < 4; c++)
                acc[mt][nt][c] = fmaxf(acc[mt][nt][c], 0.f);

    if (EMODE == 1 || EMODE == 3){
        float* Cb = C + (size_t)bz * strC;
#pragma unroll
        for (int mt = 0; mt < 4; mt++)
#pragma unroll
            for (int nt = 0; nt < 4; nt++)
#pragma unroll
                for (int d = 0; d < 2; d++){
                    int p   = m0 + wm * 64 + mt * 16 + r0 + 8 * d;
                    int col = n0 + wn * 32 + nt * 8 + 2 * (lane & 3);
                    *reinterpret_cast<float2*>(Cb + (size_t)p * 1024 + col) =
                        make_float2(acc[mt][nt][2 * d], acc[mt][nt][2 * d + 1]);
                }
    }

    if (EMODE == 1 || EMODE == 2){
        // smem transpose to fp16: [p][hw] tile -> [hw][p], row stride 136 halfs
        __half* sh = (__half*)smem_raw;
        __syncthreads();
#pragma unroll
        for (int mt = 0; mt < 4; mt++)
#pragma unroll
            for (int nt = 0; nt < 4; nt++)
#pragma unroll
                for (int c = 0; c < 4; c++){
                    int rl = wm * 64 + mt * 16 + r0 + 8 * (c >> 1);
                    int cl = wn * 32 + nt * 8 + 2 * (lane & 3) + (c & 1);
                    sh[cl * 136 + rl] = __float2half_rn(acc[mt][nt][c]);
                }
        __syncthreads();
        __half* C2b = C2 + (size_t)bz * strC2;
#pragma unroll
        for (int q = 0; q < 8; q++){
            int s = q * 256 + tid;            // 2048 16B segments
            int hw = s >> 4, seg = s & 15;
            uint4 v = *reinterpret_cast<const uint4*>(sh + hw * 136 + seg * 8);
            *reinterpret_cast<uint4*>(C2b + (size_t)(n0 + hw) * 256 + m0 + seg * 8) = v;
        }
    }
}

// ---------------- x [b][c][hw] fp32 -> xh [b][hw][c] fp16 ----------------
__global__ void xh_k(const float* __restrict__ x, __half* __restrict__ xh)
{
    __shared__ float t[32][33];
    int b = blockIdx.z;
    int c0 = blockIdx.x * 32, h0 = blockIdx.y * 32;
    const float* xb = x + (size_t)b * 1048576;
    __half* xhb = xh + (size_t)b * 1048576;
#pragma unroll
    for (int i = 0; i < 32; i += 8)
        t[threadIdx.y + i][threadIdx.x] = xb[(size_t)(c0 + threadIdx.y + i) * 1024 + h0 + threadIdx.x];
    __syncthreads();
#pragma unroll
    for (int i = 0; i < 32; i += 8)
        xhb[(size_t)(h0 + threadIdx.y + i) * 1024 + c0 + threadIdx.x] =
            __float2half_rn(t[threadIdx.x][threadIdx.y + i]);
}

// ---------------- fp32 -> fp16 (vectorized) ----------------
__global__ void cvt16_k(const float4* __restrict__ s, __half2* __restrict__ d, int n4)
{
    int i = blockIdx.x * blockDim.x + threadIdx.x;
    if (i < n4){
        float4 v = s[i];
        d[2 * i]     = __floats2half2_rn(v.x, v.y);
        d[2 * i + 1] = __floats2half2_rn(v.z, v.w);
    }
}

// ---------------- w2 [O][C][3][3] -> w2h [O][tap*256+c] fp16 ----------------
__global__ void w2h_k(const float* __restrict__ w2, __half* __restrict__ w2h)
{
    long i = (long)blockIdx.x * 256 + threadIdx.x;
    if (i >= 256L * 2304) return;
    int o = (int)(i / 2304); int r = (int)(i % 2304);
    int k = r / 256; int c = r % 256;
    w2h[i] = __float2half_rn(w2[(long)o * 2304 + c * 9 + k]);
}

// ---------------- offset conv: 3x3, 256->18, pad 1, +bias (fp32) ----------------
__global__ void offconv_k(const float* __restrict__ h1, const float* __restrict__ ow,
                          const float* __restrict__ ob, float* __restrict__ off)
{
    extern __shared__ float sm[];
    float* wsm  = sm;           // 10368 floats
    float* slab = sm + 10368;   // 9216 floats

    int b  = blockIdx.x >> 4;
    int yp = blockIdx.x & 15;
    int tid = threadIdx.x;
    int r   = tid / 144;
    int rem = tid % 144;
    int oc  = rem / 8;
    int xg  = rem % 8;

    float a0 = 0.f, a1 = 0.f, a2 = 0.f, a3 = 0.f;
    const float* h1b = h1 + (long)b * (256 * 1024);

    for (int cc = 0; cc < 256; cc += 64){
        __syncthreads();
        for (int f = tid; f < 10368; f += 288){
            int c = f / 162; int r1 = f % 162; int o2 = r1 / 9; int kk = r1 % 9;
            wsm[f] = ow[((long)o2 * 256 + cc + c) * 9 + kk];
        }
        for (int f = tid; f < 9216; f += 288){
            int c = f / 144; int rr2 = (f % 144) / 36; int xx = f % 36;
            int gy = yp * 2 - 1 + rr2;
            int gx = xx - 1;
            float vv = 0.f;
            if (gy >= 0 && gy < 32 && gx >= 0 && gx < 32)
                vv = h1b[(long)(cc + c) * 1024 + gy * 32 + gx];
            slab[f] = vv;
        }
        __syncthreads();
#pragma unroll 4
        for (int c = 0; c < 64; c++){
            const float* wp = &wsm[c * 162 + oc * 9];
            const float* sp = &slab[c * 144 + r * 36 + xg * 4];
#pragma unroll
            for (int ky = 0; ky < 3; ky++){
                const float* q = sp + ky * 36;
                float s_0 = q[0], s_1 = q[1], s_2 = q[2], s_3 = q[3], s_4 = q[4], s_5 = q[5];
                float w0 = wp[ky*3+0], w1 = wp[ky*3+1], w2v = wp[ky*3+2];
                a0 += s_0*w0 + s_1*w1 + s_2*w2v;
                a1 += s_1*w0 + s_2*w1 + s_3*w2v;
                a2 += s_2*w0 + s_3*w1 + s_4*w2v;
                a3 += s_3*w0 + s_4*w1 + s_5*w2v;
            }
        }
    }
    int yq = yp * 2 + r;
    float bias = ob[oc];
    float* op = off + (long)b * (18 * 1024) + (long)oc * 1024 + yq * 32 + xg * 4;
    op[0] = a0 + bias; op[1] = a1 + bias; op[2] = a2 + bias; op[3] = a3 + bias;
}

// ---------------- bilinear gather -> im2col acch[b][hw][tap*256+c] fp16 ----------------
__global__ void gather_k(const __half* __restrict__ h1t, const float* __restrict__ off,
                         __half* __restrict__ acc)
{
    int b = blockIdx.x >> 5;
    int y = blockIdx.x & 31;
    int lane = threadIdx.x & 63;
    int jg   = threadIdx.x >> 6;
    const __half* h1b = h1t + (size_t)b * (1024 * 256);
    const float* offb = off + (size_t)b * (18 * 1024);
    __half* accb = acc + (size_t)b * (1024L * 2304);

    for (int j = jg; j < 288; j += 4){
        int k = j >> 5;
        int x = j & 31;
        int pix = y * 32 + x;
        float oy = offb[(2*k  ) * 1024 + pix];
        float ox = offb[(2*k+1) * 1024 + pix];
        float py = (float)y + (float)(k / 3 - 1) + oy;
        float px = (float)x + (float)(k % 3 - 1) + ox;
        float y0f = floorf(py), x0f = floorf(px);
        float wy = py - y0f, wx = px - x0f;

        float r0 = 0.f, r1 = 0.f, r2 = 0.f, r3 = 0.f;
#pragma unroll
        for (int dy = 0; dy < 2; dy++)
#pragma unroll
        for (int dx = 0; dx < 2; dx++){
            float yi = y0f + (float)dy, xi = x0f + (float)dx;
            float w = (dy ? wy : 1.f - wy) * (dx ? wx : 1.f - wx);
            bool valid = (yi >= 0.f) && (yi <= 31.f) && (xi >= 0.f) && (xi <= 31.f);
            w = valid ? w : 0.f;
            int yic = (int)fminf(fmaxf(yi, 0.f), 31.f);
            int xic = (int)fminf(fmaxf(xi, 0.f), 31.f);
            const __half2* hp = reinterpret_cast<const __half2*>(
                h1b + (size_t)(yic * 32 + xic) * 256 + lane * 4);
            float2 f0 = __half22float2(hp[0]);
            float2 f1 = __half22float2(hp[1]);
            r0 = fmaf(w, f0.x, r0); r1 = fmaf(w, f0.y, r1);
            r2 = fmaf(w, f1.x, r2); r3 = fmaf(w, f1.y, r3);
        }
        __half2 o0 = __floats2half2_rn(r0, r1);
        __half2 o1 = __floats2half2_rn(r2, r3);
        uint2 st;
        st.x = *reinterpret_cast<uint32_t*>(&o0);
        st.y = *reinterpret_cast<uint32_t*>(&o1);
        *reinterpret_cast<uint2*>(accb + (size_t)pix * 2304 + k * 256 + lane * 4) = st;
    }
}

// ---------------- launch ----------------
extern "C" void kernel_launch(void* const* d_in, const int* in_sizes, int n_in,
                              void* d_out, int out_size)
{
    const float* x    = (const float*)d_in[0];
    const float* w1   = (const float*)d_in[1];
    const float* bn1g = (const float*)d_in[2];
    const float* bn1b = (const float*)d_in[3];
    const float* bn1m = (const float*)d_in[4];
    const float* bn1v = (const float*)d_in[5];
    const float* offw = (const float*)d_in[6];
    const float* offb = (const float*)d_in[7];
    const float* w2   = (const float*)d_in[8];
    const float* bn2g = (const float*)d_in[9];
    const float* bn2b = (const float*)d_in[10];
    const float* bn2m = (const float*)d_in[11];
    const float* bn2v = (const float*)d_in[12];
    const float* w3   = (const float*)d_in[13];
    const float* bn3g = (const float*)d_in[14];
    const float* bn3b = (const float*)d_in[15];
    const float* bn3m = (const float*)d_in[16];
    const float* bn3v = (const float*)d_in[17];
    float* out = (float*)d_out;

    float  *p_h1, *p_off;
    __half *p_h1t, *p_h2h, *p_w1h, *p_w2h, *p_w3h, *p_xh, *p_acch;
    cudaGetSymbolAddress((void**)&p_h1,   g_h1);
    cudaGetSymbolAddress((void**)&p_h1t,  g_h1t);
    cudaGetSymbolAddress((void**)&p_off,  g_off);
    cudaGetSymbolAddress((void**)&p_h2h,  g_h2h);
    cudaGetSymbolAddress((void**)&p_w1h,  g_w1h);
    cudaGetSymbolAddress((void**)&p_w2h,  g_w2h);
    cudaGetSymbolAddress((void**)&p_w3h,  g_w3h);
    cudaGetSymbolAddress((void**)&p_xh,   g_xh);
    cudaGetSymbolAddress((void**)&p_acch, g_acch);

    cudaFuncSetAttribute(offconv_k, cudaFuncAttributeMaxDynamicSharedMemorySize, 78336);
    cudaFuncSetAttribute(tgemm_h<1024,1>, cudaFuncAttributeMaxDynamicSharedMemorySize, TGH_SMEM);
    cudaFuncSetAttribute(tgemm_h<2304,2>, cudaFuncAttributeMaxDynamicSharedMemorySize, TGH_SMEM);
    cudaFuncSetAttribute(tgemm_h<256,3>,  cudaFuncAttributeMaxDynamicSharedMemorySize, TGH_SMEM);

    // operand prep: fp16 conversion (+ transpose/permute where needed)
    xh_k<<<dim3(32, 32, 16), dim3(32, 8)>>>(x, p_xh);
    cvt16_k<<<256, 256>>>((const float4*)w1, (__half2*)p_w1h, 256 * 1024 / 4);
    cvt16_k<<<256, 256>>>((const float4*)w3, (__half2*)p_w3h, 1024 * 256 / 4);
    w2h_k<<<2304, 256>>>(w2, p_w2h);

    // conv1x1 (1024->256) + BN1 + ReLU -> h1 fp32 [p][hw] + h1t fp16 [hw][p]
    tgemm_h<1024,1><<<dim3(8, 2, 16), 256, TGH_SMEM>>>(
        p_w1h, p_xh, 1048576L, p_h1, 262144L,
        bn1g, bn1b, bn1m, bn1v, nullptr, 0, p_h1t, 262144L);

    // offset conv 3x3 (256->18) + bias (fp32)
    offconv_k<<<256, 288, 78336>>>(p_h1, offw, offb, p_off);

    // deformable bilinear gather -> fp16 im2col
    gather_k<<<512, 256>>>(p_h1t, p_off, p_acch);

    // deform conv GEMM K=2304 + BN2 + ReLU -> h2h fp16 [hw][p]
    tgemm_h<2304,2><<<dim3(8, 2, 16), 256, TGH_SMEM>>>(
        p_w2h, p_acch, 2359296L, nullptr, 0,
        bn2g, bn2b, bn2m, bn2v, nullptr, 0, p_h2h, 262144L);

    // conv1x1 (256->1024) + BN3 + shortcut + ReLU -> d_out (fp32)
    tgemm_h<256,3><<<dim3(8, 8, 16), 256, TGH_SMEM>>>(
        p_w3h, p_h2h, 262144L, out, 1048576L,
        bn3g, bn3b, bn3m, bn3v, x, 1048576L, nullptr, 0);

    (void)in_sizes; (void)n_in; (void)out_size;
}